// round 6
// baseline (speedup 1.0000x reference)
#include <cuda_runtime.h>
#include <cstdint>
#include <cstddef>

// CTC loss (faithful to reference incl. input_len = C bug).
// B=512, T=512 (row stride), C=128, Tu=128, L=64, S=129, blank=127.
// Warp per row; lane holds states 4*lane+j (j=0..3), lane31 also state 128.
// Linear domain + power-of-2 rescale per 8 steps; 128 uniform steps from
// virtual init a0=1@lane0. Recursion in PACKED f32x2 (sm_100a):
//   (a0,a2),(a1,a3) as 64-bit pairs -> 4 packed + 2 scalar fma-ops per step.
// q-values register-pipelined one chunk ahead via cp.async staging.

#define B_    512
#define T_    512
#define C_    128
#define L_    64
#define BLANK 127
#define EPSF  (1e-7f)
#define LN2F  0.69314718055994530942f

#define WARPS  2
#define CHUNK  8
#define NBUF   4
#define NCHUNK 16        // 128 timesteps / CHUNK

__device__ __forceinline__ void cpasync16(uint32_t saddr, const void* g) {
    asm volatile("cp.async.cg.shared.global [%0], [%1], 16;" :: "r"(saddr), "l"(g));
}
__device__ __forceinline__ void cp_commit() { asm volatile("cp.async.commit_group;"); }
__device__ __forceinline__ void cp_wait2()  { asm volatile("cp.async.wait_group 2;"); }
__device__ __forceinline__ void cp_wait0()  { asm volatile("cp.async.wait_group 0;"); }

// ---- packed f32x2 helpers (sm_100a) ----------------------------------------
__device__ __forceinline__ uint64_t pk(float lo, float hi) {
    uint64_t r; asm("mov.b64 %0, {%1, %2};" : "=l"(r) : "f"(lo), "f"(hi)); return r;
}
__device__ __forceinline__ void upk(uint64_t v, float& lo, float& hi) {
    asm("mov.b64 {%0, %1}, %2;" : "=f"(lo), "=f"(hi) : "l"(v));
}
__device__ __forceinline__ uint64_t add2(uint64_t a, uint64_t b) {
    uint64_t r; asm("add.rn.f32x2 %0, %1, %2;" : "=l"(r) : "l"(a), "l"(b)); return r;
}
__device__ __forceinline__ uint64_t mul2(uint64_t a, uint64_t b) {
    uint64_t r; asm("mul.rn.f32x2 %0, %1, %2;" : "=l"(r) : "l"(a), "l"(b)); return r;
}
__device__ __forceinline__ uint64_t fma2(uint64_t a, uint64_t b, uint64_t c) {
    uint64_t r; asm("fma.rn.f32x2 %0, %1, %2, %3;" : "=l"(r) : "l"(a), "l"(b), "l"(c)); return r;
}

struct Q { uint64_t q01, qBB, p13; float qBs; };

__global__ __launch_bounds__(WARPS * 32)
void ctc_kernel(const int* __restrict__ y_true,
                const float* __restrict__ y_pred,
                float* __restrict__ out)
{
    const unsigned FULL = 0xffffffffu;
    const int lane = threadIdx.x & 31;
    const int w    = threadIdx.x >> 5;
    const int b    = blockIdx.x * WARPS + w;

    __shared__ float sm[WARPS][NBUF][CHUNK][C_];
    const uint32_t smbase = (uint32_t)__cvta_generic_to_shared(&sm[w][0][0][0]);

    const float* __restrict__ row = y_pred + (size_t)b * T_ * C_;

    // labels (coalesced int2): lane -> labels 2*lane, 2*lane+1
    const int2 lpair = ((const int2*)(y_true + b * L_))[lane];
    const int l0 = lpair.x, l1 = lpair.y;
    const int lp = __shfl_up_sync(FULL, l1, 1);
    const float sk1 = (lane > 0 && l0 != lp) ? 1.f : 0.f;  // state 4l+1 skip
    const float sk3 = (l1 != l0) ? 1.f : 0.f;              // state 4l+3 skip
    const uint64_t SK   = pk(sk1, sk3);
    const uint64_t EPS2 = pk(EPSF, EPSF);

    // ---- staging helpers ----------------------------------------------------
    auto stage = [&](int c) {
        const float* g = row + (size_t)c * CHUNK * C_ + lane * 4;
        const uint32_t s = smbase +
            (uint32_t)(((c & (NBUF - 1)) * CHUNK * C_ + lane * 4) * 4);
        #pragma unroll
        for (int j = 0; j < CHUNK; ++j)
            cpasync16(s + j * C_ * 4, g + j * C_);
        cp_commit();
    };
    auto ldq = [&](int c, Q* q) {
        const float* srow = &sm[w][c & (NBUF - 1)][0][0];
        #pragma unroll
        for (int j = 0; j < CHUNK; ++j) {
            const float q0 = srow[j * C_ + l0];
            const float q1 = srow[j * C_ + l1];
            const float qB = srow[j * C_ + BLANK] + EPSF;
            q[j].q01 = add2(pk(q0, q1), EPS2);     // (q0+eps, q1+eps)
            q[j].qBB = pk(qB, qB);
            q[j].p13 = mul2(SK, q[j].q01);         // (sk1*q0, sk3*q1)
            q[j].qBs = qB;
        }
    };

    // ---- alpha state (packed): virtual init => 128 uniform steps ------------
    uint64_t P02 = pk((lane == 0) ? 1.f : 0.f, 0.f);   // (a0, a2)
    uint64_t P13 = pk(0.f, 0.f);                       // (a1, a3)
    float a4 = 0.f;                                    // state 128 (lane 31)
    float n3 = 0.f;                                    // neighbor a3
    int etot = 0;

    auto steps = [&](const Q* q) {
        #pragma unroll
        for (int j = 0; j < CHUNK; ++j) {
            float a1s, a3s; upk(P13, a1s, a3s);
            const uint64_t X   = pk(n3, a1s);          // (n3, a1)
            const uint64_t S1  = add2(P02, X);         // (a0+n3, a2+a1)
            const uint64_t S2  = add2(P13, P02);       // (a1+a0, a3+a2)
            const uint64_t H   = mul2(X, q[j].p13);    // (p1*n3, p3*a1)
            P02 = mul2(S1, q[j].qBB);                  // (na0, na2)
            P13 = fma2(S2, q[j].q01, H);               // (na1, na3)
            a4  = (a4 + a3s) * q[j].qBs;               // na4 (state 128)
            float na1s, na3s; upk(P13, na1s, na3s);
            const float t = __shfl_up_sync(FULL, na3s, 1);   // early issue
            n3 = (lane == 0) ? 0.f : t;
        }
        // power-of-two rescale (alpha >= 0 -> float bits monotonic as s32)
        float x0, x2, x1, x3;
        upk(P02, x0, x2); upk(P13, x1, x3);
        float mv = fmaxf(fmaxf(x0, x1), fmaxf(fmaxf(x2, x3), a4));
        int rb;
        asm volatile("redux.sync.max.s32 %0, %1, 0xffffffff;"
                     : "=r"(rb) : "r"(__float_as_int(mv)));
        const int e = (rb >> 23) - 127;
        const float sc = __int_as_float((127 - e) << 23);    // 2^-e
        const uint64_t SC = pk(sc, sc);
        P02 = mul2(P02, SC);
        P13 = mul2(P13, SC);
        a4 *= sc; n3 *= sc;
        etot += e;
    };

    // ---- pipeline prologue --------------------------------------------------
    stage(0); stage(1); stage(2);
    cp_wait2(); __syncwarp();
    Q qa[CHUNK], qb[CHUNK];
    ldq(0, qa);

    // ---- main loop: chunk pairs (ping-pong register sets) -------------------
    for (int p = 0; p < NCHUNK / 2; ++p) {
        const int c = 2 * p;
        if (c + 3 < NCHUNK) { stage(c + 3); cp_wait2(); } else { cp_wait0(); }
        __syncwarp();
        ldq(c + 1, qb);
        steps(qa);
        const int c2 = c + 1;
        if (c2 + 3 < NCHUNK) { stage(c2 + 3); cp_wait2(); } else { cp_wait0(); }
        __syncwarp();
        if (c2 + 1 < NCHUNK) ldq(c2 + 1, qa);
        steps(qb);
    }

    // ---- loss = -( ln(alpha[127] + alpha[128]) + etot*ln2 ) -----------------
    if (lane == 31) {
        float a1s, a3s; upk(P13, a1s, a3s);
        const float s = a3s + a4;          // states 127, 128
        out[b] = -(__logf(s) + (float)etot * LN2F);
    }
}

extern "C" void kernel_launch(void* const* d_in, const int* in_sizes, int n_in,
                              void* d_out, int out_size)
{
    const int* y_true;
    const float* y_pred;
    if (n_in >= 2 && in_sizes[0] == B_ * L_) {
        y_true = (const int*)d_in[0];
        y_pred = (const float*)d_in[1];
    } else {
        y_true = (const int*)d_in[1];
        y_pred = (const float*)d_in[0];
    }
    float* out = (float*)d_out;

    ctc_kernel<<<B_ / WARPS, WARPS * 32>>>(y_true, y_pred, out);
}

// round 7
// speedup vs baseline: 1.2025x; 1.2025x over previous
#include <cuda_runtime.h>
#include <cstdint>
#include <cstddef>

// CTC loss (faithful to reference incl. input_len = C bug).
// B=512, T=512 (row stride), C=128, Tu=128, L=64, S=129, blank=127.
// One 32-thread block per batch row. Lane holds states 4*lane+j (j=0..3),
// lane31 also state 128. Linear domain, power-of-2 rescale per 8 steps,
// 128 uniform steps from virtual init a0=1@lane0 (scalar recursion).
// cp.async staging with DEEP pipeline: 8-buffer ring, prefetch distance 5,
// wait_group 4 (~2000 cyc of cover vs loaded-DRAM latency).

#define B_    512
#define T_    512
#define C_    128
#define L_    64
#define BLANK 127
#define EPSF  (1e-7f)
#define LN2F  0.69314718055994530942f

#define CHUNK  8
#define NBUF   8
#define NCHUNK 16        // 128 timesteps / CHUNK
#define DEPTH  5         // chunks staged ahead

__device__ __forceinline__ void cpasync16(uint32_t saddr, const void* g) {
    asm volatile("cp.async.cg.shared.global [%0], [%1], 16;" :: "r"(saddr), "l"(g));
}
__device__ __forceinline__ void cp_commit() { asm volatile("cp.async.commit_group;"); }
__device__ __forceinline__ void cp_wait4()  { asm volatile("cp.async.wait_group 4;"); }

struct Q { float q0, q1, qB, p1, p3; };

__global__ __launch_bounds__(32)
void ctc_kernel(const int* __restrict__ y_true,
                const float* __restrict__ y_pred,
                float* __restrict__ out)
{
    const unsigned FULL = 0xffffffffu;
    const int lane = threadIdx.x & 31;
    const int b    = blockIdx.x;

    __shared__ float sm[NBUF][CHUNK][C_];
    const uint32_t smbase = (uint32_t)__cvta_generic_to_shared(&sm[0][0][0]);

    const float* __restrict__ row = y_pred + (size_t)b * T_ * C_;

    // labels (coalesced int2): lane -> labels 2*lane, 2*lane+1
    const int2 lpair = ((const int2*)(y_true + b * L_))[lane];
    const int l0 = lpair.x, l1 = lpair.y;
    const int lp = __shfl_up_sync(FULL, l1, 1);
    const float sk1 = (lane > 0 && l0 != lp) ? 1.f : 0.f;   // state 4l+1 skip
    const float sk3 = (l1 != l0) ? 1.f : 0.f;               // state 4l+3 skip

    // ---- staging helpers ----------------------------------------------------
    auto issue_chunk = [&](int c) {
        const float* g = row + (size_t)c * CHUNK * C_ + lane * 4;
        const uint32_t s = smbase +
            (uint32_t)(((c & (NBUF - 1)) * CHUNK * C_ + lane * 4) * 4);
        #pragma unroll
        for (int j = 0; j < CHUNK; ++j)
            cpasync16(s + j * C_ * 4, g + j * C_);
    };
    auto ldq = [&](int c, Q* q) {
        const float* srow = &sm[c & (NBUF - 1)][0][0];
        #pragma unroll
        for (int j = 0; j < CHUNK; ++j) {
            q[j].q0 = srow[j * C_ + l0]    + EPSF;
            q[j].q1 = srow[j * C_ + l1]    + EPSF;
            q[j].qB = srow[j * C_ + BLANK] + EPSF;
            q[j].p1 = sk1 * q[j].q0;
            q[j].p3 = sk3 * q[j].q1;
        }
    };

    // ---- alpha state: virtual init => 128 uniform steps ---------------------
    float a0 = (lane == 0) ? 1.f : 0.f;
    float a1 = 0.f, a2 = 0.f, a3 = 0.f, a4 = 0.f;
    float n3 = 0.f;             // neighbor a3 (pre-shfl'd for upcoming step)
    int etot = 0;

    auto steps = [&](const Q* q) {
        #pragma unroll
        for (int j = 0; j < CHUNK; ++j) {
            const float na0 = (a0 + n3) * q[j].qB;                // s=4l (blank)
            const float na1 = fmaf(a1 + a0, q[j].q0, q[j].p1 * n3);
            const float na2 = (a2 + a1) * q[j].qB;                // blank
            const float na3 = fmaf(a3 + a2, q[j].q1, q[j].p3 * a1);
            const float na4 = (a4 + a3) * q[j].qB;                // s=128
            a0 = na0; a1 = na1; a2 = na2; a3 = na3; a4 = na4;
            const float t = __shfl_up_sync(FULL, a3, 1);          // early issue
            n3 = (lane == 0) ? 0.f : t;
        }
        // power-of-two rescale (alpha >= 0 -> float bits monotonic as s32)
        float mv = fmaxf(fmaxf(a0, a1), fmaxf(fmaxf(a2, a3), a4));
        int rb;
        asm volatile("redux.sync.max.s32 %0, %1, 0xffffffff;"
                     : "=r"(rb) : "r"(__float_as_int(mv)));
        const int e = (rb >> 23) - 127;
        const float sc = __int_as_float((127 - e) << 23);         // 2^-e
        a0 *= sc; a1 *= sc; a2 *= sc; a3 *= sc; a4 *= sc; n3 *= sc;
        etot += e;
    };

    // ---- pipeline prologue: stage chunks 0..DEPTH-1 -------------------------
    #pragma unroll
    for (int k = 0; k < DEPTH; ++k) { issue_chunk(k); cp_commit(); }
    cp_wait4(); __syncwarp();           // chunk 0 resident
    Q qa[CHUNK], qb[CHUNK];
    ldq(0, qa);

    // ---- main loop: chunk pairs (ping-pong register sets) -------------------
    // loop iteration i: one commit; after wait_group 4, chunks 0..i+1 resident.
    for (int p = 0; p < NCHUNK / 2; ++p) {
        const int c = 2 * p;
        if (c + DEPTH < NCHUNK) issue_chunk(c + DEPTH);
        cp_commit();
        cp_wait4(); __syncwarp();
        ldq(c + 1, qb);                 // c+1 <= 15
        steps(qa);

        const int c2 = c + 1;
        if (c2 + DEPTH < NCHUNK) issue_chunk(c2 + DEPTH);
        cp_commit();
        cp_wait4(); __syncwarp();
        if (c2 + 1 < NCHUNK) ldq(c2 + 1, qa);
        steps(qb);
    }

    // ---- loss = -( ln(alpha[127] + alpha[128]) + etot*ln2 ) -----------------
    if (lane == 31) {
        const float s = a3 + a4;        // states 127, 128
        out[b] = -(__logf(s) + (float)etot * LN2F);
    }
}

extern "C" void kernel_launch(void* const* d_in, const int* in_sizes, int n_in,
                              void* d_out, int out_size)
{
    const int* y_true;
    const float* y_pred;
    if (n_in >= 2 && in_sizes[0] == B_ * L_) {
        y_true = (const int*)d_in[0];
        y_pred = (const float*)d_in[1];
    } else {
        y_true = (const int*)d_in[1];
        y_pred = (const float*)d_in[0];
    }
    float* out = (float*)d_out;

    ctc_kernel<<<B_, 32>>>(y_true, y_pred, out);
}